// round 1
// baseline (speedup 1.0000x reference)
#include <cuda_runtime.h>
#include <math.h>

// Problem constants
#define BATCH 256
#define TT    256           // sequence length
#define DM    384
#define DKV   64            // dk == dv == 64
#define BT    (BATCH*TT)    // 65536 rows

// ---------------------------------------------------------------------------
// Scratch (static device allocations are the allowed scratch mechanism)
// ---------------------------------------------------------------------------
__device__ float g_q[BT * DKV];
__device__ float g_k[BT * DKV];
__device__ float g_v[BT * DKV];

// ---------------------------------------------------------------------------
// Kernel 1: fused QKV projection.
//   C_{q,k,v}[BT,64] = X[BT,384] * W_{q,k,v}[384,64]
// One block computes a 64-row stripe against ALL THREE weight matrices so X
// is read from HBM exactly once. BM=64, BN=192 (3x64), BK=32.
// 256 threads = 16x16; each thread owns a 4x12 microtile (48 accumulators).
// ---------------------------------------------------------------------------
#define BM 64
#define BK 32

__global__ __launch_bounds__(256) void proj_kernel(
    const float* __restrict__ X,
    const float* __restrict__ Wq,
    const float* __restrict__ Wk,
    const float* __restrict__ Wv)
{
    __shared__ float Xs[BM][BK + 1];   // +1 pad: conflict-free column reads
    __shared__ float Ws[BK][192];      // 3 weight tiles side by side

    const int tid = threadIdx.x;
    const int tx  = tid & 15;          // 0..15 -> output col group (x4)
    const int ty  = tid >> 4;          // 0..15 -> output row group (x4)
    const int row0 = blockIdx.x * BM;

    const float* Wsrc[3] = { Wq, Wk, Wv };

    float acc[4][12];
    #pragma unroll
    for (int i = 0; i < 4; i++)
        #pragma unroll
        for (int j = 0; j < 12; j++) acc[i][j] = 0.f;

    for (int k0 = 0; k0 < DM; k0 += BK) {
        // ---- load X tile 64x32 (coalesced float4, scalar smem stores) ----
        {
            const int lc = (tid & 7) * 4;   // col within tile
            const int lr = tid >> 3;        // 0..31
            #pragma unroll
            for (int rr = 0; rr < 2; rr++) {
                const int r = lr + rr * 32;
                float4 v = *(const float4*)&X[(size_t)(row0 + r) * DM + k0 + lc];
                Xs[r][lc + 0] = v.x; Xs[r][lc + 1] = v.y;
                Xs[r][lc + 2] = v.z; Xs[r][lc + 3] = v.w;
            }
        }
        // ---- load 3 W tiles, each 32x64 ----
        {
            const int wc = (tid & 15) * 4;
            const int wr = tid >> 4;        // 0..15
            #pragma unroll
            for (int p = 0; p < 3; p++) {
                const float* W = Wsrc[p];
                #pragma unroll
                for (int rr = 0; rr < 2; rr++) {
                    const int r = wr + rr * 16;
                    *(float4*)&Ws[r][p * 64 + wc] =
                        *(const float4*)&W[(size_t)(k0 + r) * DKV + wc];
                }
            }
        }
        __syncthreads();

        #pragma unroll
        for (int kk = 0; kk < BK; kk++) {
            float a[4];
            #pragma unroll
            for (int i = 0; i < 4; i++) a[i] = Xs[ty * 4 + i][kk];
            #pragma unroll
            for (int p = 0; p < 3; p++) {
                float4 bv = *(const float4*)&Ws[kk][p * 64 + tx * 4];
                #pragma unroll
                for (int i = 0; i < 4; i++) {
                    acc[i][p * 4 + 0] += a[i] * bv.x;
                    acc[i][p * 4 + 1] += a[i] * bv.y;
                    acc[i][p * 4 + 2] += a[i] * bv.z;
                    acc[i][p * 4 + 3] += a[i] * bv.w;
                }
            }
        }
        __syncthreads();
    }

    float* Cdst[3] = { g_q, g_k, g_v };
    #pragma unroll
    for (int p = 0; p < 3; p++) {
        #pragma unroll
        for (int i = 0; i < 4; i++) {
            const int r = row0 + ty * 4 + i;
            float4 o = make_float4(acc[i][p * 4 + 0], acc[i][p * 4 + 1],
                                   acc[i][p * 4 + 2], acc[i][p * 4 + 3]);
            *(float4*)&Cdst[p][(size_t)r * DKV + tx * 4] = o;
        }
    }
}

// ---------------------------------------------------------------------------
// Kernel 2: causal attention, one block per batch, one thread per query.
// Full K and V for the batch live in shared memory (128 KB). All smem reads
// inside the j-loop are warp-uniform -> broadcast (no bank conflicts).
// Online (flash-style) softmax keeps everything in registers.
//
// Warp->query-block remap {0,1,2,3,7,6,5,4}: warps w and w+4 share an SMSP;
// pairing low-trip-count blocks with high ones balances all 4 SMSPs.
// ---------------------------------------------------------------------------
__global__ __launch_bounds__(256, 1) void attn_kernel(float* __restrict__ out)
{
    extern __shared__ float smem[];
    float* Ks = smem;                // [256][64]
    float* Vs = smem + TT * DKV;     // [256][64]

    const int b   = blockIdx.x;
    const int tid = threadIdx.x;

    const float* Kb = g_k + (size_t)b * TT * DKV;
    const float* Vb = g_v + (size_t)b * TT * DKV;

    // cooperative load of K and V (float4, coalesced)
    for (int i = tid; i < TT * DKV / 4; i += 256) {
        ((float4*)Ks)[i] = ((const float4*)Kb)[i];
        ((float4*)Vs)[i] = ((const float4*)Vb)[i];
    }

    // SMSP load-balancing remap: warp w handles query block qb
    const int wid  = tid >> 5;
    const int lane = tid & 31;
    const int qb   = (wid < 4) ? wid : (11 - wid);
    const int t    = qb * 32 + lane;         // query index (permutation of 0..255)

    // load q (pre-scaled by dk^-0.5 = 0.125)
    float q[DKV];
    {
        const float* Qr = g_q + ((size_t)b * TT + t) * DKV;
        #pragma unroll
        for (int d = 0; d < DKV; d++) q[d] = Qr[d] * 0.125f;
    }
    __syncthreads();

    float m = -1e30f, l = 0.f;
    float acc[DKV];
    #pragma unroll
    for (int d = 0; d < DKV; d++) acc[d] = 0.f;

    for (int j = 0; j <= t; j++) {
        // score = q . K[j]
        float s = 0.f;
        const float4* kr = (const float4*)(Ks + j * DKV);
        #pragma unroll
        for (int d4 = 0; d4 < 16; d4++) {
            float4 kv = kr[d4];
            s += q[d4 * 4 + 0] * kv.x + q[d4 * 4 + 1] * kv.y
               + q[d4 * 4 + 2] * kv.z + q[d4 * 4 + 3] * kv.w;
        }
        const float mnew  = fmaxf(m, s);
        const float scale = __expf(m - mnew);   // 0 on first iter (m=-1e30)
        const float p     = __expf(s - mnew);
        l = l * scale + p;
        const float4* vr = (const float4*)(Vs + j * DKV);
        #pragma unroll
        for (int d4 = 0; d4 < 16; d4++) {
            float4 vv = vr[d4];
            acc[d4 * 4 + 0] = acc[d4 * 4 + 0] * scale + p * vv.x;
            acc[d4 * 4 + 1] = acc[d4 * 4 + 1] * scale + p * vv.y;
            acc[d4 * 4 + 2] = acc[d4 * 4 + 2] * scale + p * vv.z;
            acc[d4 * 4 + 3] = acc[d4 * 4 + 3] * scale + p * vv.w;
        }
        m = mnew;
    }

    const float inv = 1.f / l;
    float* o = out + ((size_t)b * TT + t) * DKV;
    #pragma unroll
    for (int d4 = 0; d4 < 16; d4++) {
        float4 ov = make_float4(acc[d4 * 4 + 0] * inv, acc[d4 * 4 + 1] * inv,
                                acc[d4 * 4 + 2] * inv, acc[d4 * 4 + 3] * inv);
        *(float4*)&o[d4 * 4] = ov;
    }
}

// ---------------------------------------------------------------------------
// kernel_launch — graph-capturable, allocation-free
// ---------------------------------------------------------------------------
extern "C" void kernel_launch(void* const* d_in, const int* in_sizes, int n_in,
                              void* d_out, int out_size)
{
    const float* x  = (const float*)d_in[0];
    const float* Wq = (const float*)d_in[1];
    const float* Wk = (const float*)d_in[2];
    const float* Wv = (const float*)d_in[3];
    float* out = (float*)d_out;

    (void)in_sizes; (void)n_in; (void)out_size;

    proj_kernel<<<dim3(BT / BM, 1, 1), 256>>>(x, Wq, Wk, Wv);

    const int attn_smem = 2 * TT * DKV * (int)sizeof(float);   // 128 KB
    cudaFuncSetAttribute(attn_kernel,
                         cudaFuncAttributeMaxDynamicSharedMemorySize, attn_smem);
    attn_kernel<<<BATCH, 256, attn_smem>>>(out);
}

// round 4
// speedup vs baseline: 1.4621x; 1.4621x over previous
#include <cuda_runtime.h>
#include <cuda_bf16.h>
#include <cstdint>

// Problem constants
#define BATCH 256
#define TT    256
#define DM    384
#define DKV   64
#define BT    (BATCH*TT)

// ---------------------------------------------------------------------------
// Scratch
// ---------------------------------------------------------------------------
__device__ float g_q[BT * DKV];
__device__ float g_k[BT * DKV];
__device__ float g_v[BT * DKV];
// W^T packed [192 n][384 k], bf16 hi / lo split. n: 0-63=Wq, 64-127=Wk, 128-191=Wv
__device__ __align__(16) __nv_bfloat16 g_wth[192 * DM];
__device__ __align__(16) __nv_bfloat16 g_wtl[192 * DM];

// ---------------------------------------------------------------------------
// PTX helpers (sm_80-era: mma.sync + ldmatrix, valid at compute_103)
// ---------------------------------------------------------------------------
__device__ __forceinline__ uint32_t smem_u32(const void* p) {
    uint32_t a;
    asm("{ .reg .u64 t; cvta.to.shared.u64 t, %1; cvt.u32.u64 %0, t; }"
        : "=r"(a) : "l"(p));
    return a;
}
__device__ __forceinline__ void ldsm_x4(uint32_t addr, uint32_t* r) {
    asm volatile("ldmatrix.sync.aligned.m8n8.x4.shared.b16 {%0,%1,%2,%3}, [%4];"
                 : "=r"(r[0]), "=r"(r[1]), "=r"(r[2]), "=r"(r[3]) : "r"(addr));
}
__device__ __forceinline__ void mma_bf16(float* c, const uint32_t* a,
                                         uint32_t b0, uint32_t b1) {
    asm volatile(
        "mma.sync.aligned.m16n8k16.row.col.f32.bf16.bf16.f32 "
        "{%0,%1,%2,%3}, {%4,%5,%6,%7}, {%8,%9}, {%0,%1,%2,%3};"
        : "+f"(c[0]), "+f"(c[1]), "+f"(c[2]), "+f"(c[3])
        : "r"(a[0]), "r"(a[1]), "r"(a[2]), "r"(a[3]), "r"(b0), "r"(b1));
}

// ---------------------------------------------------------------------------
// Kernel 0: W^T hi/lo bf16 conversion (tiny, runs once per launch)
// ---------------------------------------------------------------------------
__global__ void wconv_kernel(const float* __restrict__ Wq,
                             const float* __restrict__ Wk,
                             const float* __restrict__ Wv) {
    int idx = blockIdx.x * 256 + threadIdx.x;        // 0 .. 192*384-1
    if (idx >= 192 * DM) return;
    int n = idx / DM, k = idx % DM;
    const float* W = (n < 64) ? Wq : (n < 128) ? Wk : Wv;
    float x = W[k * DKV + (n & 63)];
    __nv_bfloat16 h = __float2bfloat16(x);
    float r = x - __bfloat162float(h);
    g_wth[idx] = h;
    g_wtl[idx] = __float2bfloat16(r);
}

// ---------------------------------------------------------------------------
// Kernel 1: fused QKV projection via mma.sync bf16 (hi/lo 3-pass).
//   C[128 rows, 192 cols] per CTA, K loop 12 x 32, smem double-buffered,
//   register-staged global loads, fp32->bf16 split on the STS path.
//   B fragment: W^T stored [n][k] (k contiguous) == col-major KxN, so
//   NON-TRANS ldmatrix delivers the mma B fragment directly.
// ---------------------------------------------------------------------------
#define BM   128
#define BN   192
#define BKS  32                  // K per stage
#define NKS  (DM / BKS)          // 12 stages
#define PAD  40                  // bf16 elements per smem row (80B stride)

// smem element offsets (bf16 units)
#define A_SZ (BM * PAD)          // 5120
#define B_SZ (BN * PAD)          // 7680
#define OFF_AH(buf) ((buf) * A_SZ)
#define OFF_AL(buf) (2 * A_SZ + (buf) * A_SZ)
#define OFF_BH(buf) (4 * A_SZ + (buf) * B_SZ)
#define OFF_BL(buf) (4 * A_SZ + 2 * B_SZ + (buf) * B_SZ)
#define SM_ELEMS    (4 * A_SZ + 4 * B_SZ)            // 51200 bf16 = 100 KB

__global__ void __launch_bounds__(256, 1) proj_mma_kernel(const float* __restrict__ X) {
    extern __shared__ __nv_bfloat16 sm[];
    const uint32_t sb = smem_u32(sm);

    const int tid    = threadIdx.x;
    const int lane   = tid & 31;
    const int wid    = tid >> 5;
    const int warp_m = wid & 3;          // 4 warps along M: 32 rows each
    const int warp_n = wid >> 2;         // 2 warps along N: 96 cols each
    const int row0   = blockIdx.x * BM;

    float acc[2][12][4];
    #pragma unroll
    for (int m = 0; m < 2; m++)
        #pragma unroll
        for (int n = 0; n < 12; n++)
            #pragma unroll
            for (int j = 0; j < 4; j++) acc[m][n][j] = 0.f;

    // staging registers
    float4 xa[4];
    uint4  bhs[3], bls[3];

    // ---- gmem load of tile ks into staging regs ----
    auto load_regs = [&](int ks) {
        const int k0 = ks * BKS;
        #pragma unroll
        for (int i = 0; i < 4; i++) {
            int f  = tid + i * 256;          // 0..1023
            int r  = f >> 3;                 // 0..127
            int c4 = f & 7;                  // 0..7 (float4 within 32 cols)
            xa[i] = *(const float4*)(X + (size_t)(row0 + r) * DM + k0 + c4 * 4);
        }
        #pragma unroll
        for (int i = 0; i < 3; i++) {
            int f  = tid + i * 256;          // 0..767
            int r  = f >> 2;                 // 0..191
            int c8 = f & 3;                  // 0..3 (uint4 = 8 bf16)
            int e  = r * DM + k0 + c8 * 8;
            bhs[i] = *(const uint4*)(g_wth + e);
            bls[i] = *(const uint4*)(g_wtl + e);
        }
    };

    // ---- convert + store staging regs into smem buffer `buf` ----
    auto store_tile = [&](int buf) {
        #pragma unroll
        for (int i = 0; i < 4; i++) {
            int f  = tid + i * 256;
            int r  = f >> 3;
            int c4 = f & 7;
            float4 v = xa[i];
            __nv_bfloat16 h0 = __float2bfloat16(v.x);
            __nv_bfloat16 h1 = __float2bfloat16(v.y);
            __nv_bfloat16 h2 = __float2bfloat16(v.z);
            __nv_bfloat16 h3 = __float2bfloat16(v.w);
            __nv_bfloat16 l0 = __float2bfloat16(v.x - __bfloat162float(h0));
            __nv_bfloat16 l1 = __float2bfloat16(v.y - __bfloat162float(h1));
            __nv_bfloat16 l2 = __float2bfloat16(v.z - __bfloat162float(h2));
            __nv_bfloat16 l3 = __float2bfloat16(v.w - __bfloat162float(h3));
            __nv_bfloat162 hp0 = __halves2bfloat162(h0, h1);
            __nv_bfloat162 hp1 = __halves2bfloat162(h2, h3);
            __nv_bfloat162 lp0 = __halves2bfloat162(l0, l1);
            __nv_bfloat162 lp1 = __halves2bfloat162(l2, l3);
            int e = r * PAD + c4 * 4;
            *(uint2*)(sm + OFF_AH(buf) + e) = make_uint2(*(uint32_t*)&hp0, *(uint32_t*)&hp1);
            *(uint2*)(sm + OFF_AL(buf) + e) = make_uint2(*(uint32_t*)&lp0, *(uint32_t*)&lp1);
        }
        #pragma unroll
        for (int i = 0; i < 3; i++) {
            int f  = tid + i * 256;
            int r  = f >> 2;
            int c8 = f & 3;
            int e  = r * PAD + c8 * 8;
            *(uint4*)(sm + OFF_BH(buf) + e) = bhs[i];
            *(uint4*)(sm + OFF_BL(buf) + e) = bls[i];
        }
    };

    // ---- pipeline ----
    load_regs(0);
    store_tile(0);
    __syncthreads();

    for (int ks = 0; ks < NKS; ks++) {
        const int cur = ks & 1;
        if (ks + 1 < NKS) load_regs(ks + 1);

        // compute on buffer `cur`
        const uint32_t ah_base = sb + OFF_AH(cur) * 2;
        const uint32_t al_base = sb + OFF_AL(cur) * 2;
        const uint32_t bh_base = sb + OFF_BH(cur) * 2;
        const uint32_t bl_base = sb + OFF_BL(cur) * 2;

        #pragma unroll
        for (int kk = 0; kk < 2; kk++) {          // two k16 sub-steps
            uint32_t ah[2][4], al[2][4];
            const int arow_l = (lane & 15);
            const int acol   = kk * 16 + ((lane >> 4) << 3);
            #pragma unroll
            for (int mt = 0; mt < 2; mt++) {
                const int arow = warp_m * 32 + mt * 16 + arow_l;
                const uint32_t aoff = (uint32_t)(arow * PAD + acol) * 2;
                ldsm_x4(ah_base + aoff, ah[mt]);
                ldsm_x4(al_base + aoff, al[mt]);
            }
            // B: lanes 0-7 -> n rows 0-7 @k0 ; 8-15 -> n0-7 @k8 ;
            //    16-23 -> n8-15 @k0 ; 24-31 -> n8-15 @k8  (non-trans)
            const int brow_l = (lane & 7) + ((lane & 16) >> 1);
            const int bcol   = kk * 16 + (lane & 8);
            #pragma unroll
            for (int g = 0; g < 6; g++) {         // 6 n16 groups = 12 n8 tiles
                uint32_t bh[4], bl[4];
                const int brow = warp_n * 96 + g * 16 + brow_l;
                const uint32_t boff = (uint32_t)(brow * PAD + bcol) * 2;
                ldsm_x4(bh_base + boff, bh);
                ldsm_x4(bl_base + boff, bl);
                #pragma unroll
                for (int mt = 0; mt < 2; mt++) {
                    #pragma unroll
                    for (int h = 0; h < 2; h++) {
                        float* c = acc[mt][g * 2 + h];
                        mma_bf16(c, ah[mt], bh[h * 2], bh[h * 2 + 1]);
                        mma_bf16(c, ah[mt], bl[h * 2], bl[h * 2 + 1]);
                        mma_bf16(c, al[mt], bh[h * 2], bh[h * 2 + 1]);
                    }
                }
            }
        }

        if (ks + 1 < NKS) {
            __syncthreads();          // everyone done reading buf (cur^1) from ks-1
            store_tile(cur ^ 1);
            __syncthreads();
        }
    }

    // ---- epilogue: fp32 accumulators -> g_q / g_k / g_v ----
    const int gi = lane >> 2;        // group id: row within tile
    const int ti = lane & 3;         // thread in group: col pair
    #pragma unroll
    for (int mt = 0; mt < 2; mt++) {
        const int row = row0 + warp_m * 32 + mt * 16 + gi;
        #pragma unroll
        for (int nt = 0; nt < 12; nt++) {
            const int col  = warp_n * 96 + nt * 8 + ti * 2;
            float* dstbase = (col < 64) ? g_q : (col < 128) ? g_k : g_v;
            float* d0 = dstbase + (size_t)row * DKV + (col & 63);
            float* d1 = dstbase + (size_t)(row + 8) * DKV + (col & 63);
            *(float2*)d0 = make_float2(acc[mt][nt][0], acc[mt][nt][1]);
            *(float2*)d1 = make_float2(acc[mt][nt][2], acc[mt][nt][3]);
        }
    }
}

// ---------------------------------------------------------------------------
// Kernel 2: causal attention (unchanged: one block/batch, K,V in smem,
// one thread per query with online softmax; SMSP-balanced warp remap)
// ---------------------------------------------------------------------------
__global__ void __launch_bounds__(256, 1) attn_kernel(float* __restrict__ out) {
    extern __shared__ float smemf[];
    float* Ks = smemf;
    float* Vs = smemf + TT * DKV;

    const int b   = blockIdx.x;
    const int tid = threadIdx.x;

    const float* Kb = g_k + (size_t)b * TT * DKV;
    const float* Vb = g_v + (size_t)b * TT * DKV;

    for (int i = tid; i < TT * DKV / 4; i += 256) {
        ((float4*)Ks)[i] = ((const float4*)Kb)[i];
        ((float4*)Vs)[i] = ((const float4*)Vb)[i];
    }

    const int wid  = tid >> 5;
    const int lane = tid & 31;
    const int qb   = (wid < 4) ? wid : (11 - wid);
    const int t    = qb * 32 + lane;

    float q[DKV];
    {
        const float* Qr = g_q + ((size_t)b * TT + t) * DKV;
        #pragma unroll
        for (int d = 0; d < DKV; d++) q[d] = Qr[d] * 0.125f;
    }
    __syncthreads();

    float m = -1e30f, l = 0.f;
    float acc[DKV];
    #pragma unroll
    for (int d = 0; d < DKV; d++) acc[d] = 0.f;

    for (int j = 0; j <= t; j++) {
        float s = 0.f;
        const float4* kr = (const float4*)(Ks + j * DKV);
        #pragma unroll
        for (int d4 = 0; d4 < 16; d4++) {
            float4 kv = kr[d4];
            s += q[d4 * 4 + 0] * kv.x + q[d4 * 4 + 1] * kv.y
               + q[d4 * 4 + 2] * kv.z + q[d4 * 4 + 3] * kv.w;
        }
        const float mnew  = fmaxf(m, s);
        const float scale = __expf(m - mnew);
        const float p     = __expf(s - mnew);
        l = l * scale + p;
        const float4* vr = (const float4*)(Vs + j * DKV);
        #pragma unroll
        for (int d4 = 0; d4 < 16; d4++) {
            float4 vv = vr[d4];
            acc[d4 * 4 + 0] = acc[d4 * 4 + 0] * scale + p * vv.x;
            acc[d4 * 4 + 1] = acc[d4 * 4 + 1] * scale + p * vv.y;
            acc[d4 * 4 + 2] = acc[d4 * 4 + 2] * scale + p * vv.z;
            acc[d4 * 4 + 3] = acc[d4 * 4 + 3] * scale + p * vv.w;
        }
        m = mnew;
    }

    const float inv = 1.f / l;
    float* o = out + ((size_t)b * TT + t) * DKV;
    #pragma unroll
    for (int d4 = 0; d4 < 16; d4++) {
        float4 ov = make_float4(acc[d4 * 4 + 0] * inv, acc[d4 * 4 + 1] * inv,
                                acc[d4 * 4 + 2] * inv, acc[d4 * 4 + 3] * inv);
        *(float4*)&o[d4 * 4] = ov;
    }
}

// ---------------------------------------------------------------------------
// kernel_launch — graph-capturable, allocation-free
// ---------------------------------------------------------------------------
extern "C" void kernel_launch(void* const* d_in, const int* in_sizes, int n_in,
                              void* d_out, int out_size) {
    const float* x  = (const float*)d_in[0];
    const float* Wq = (const float*)d_in[1];
    const float* Wk = (const float*)d_in[2];
    const float* Wv = (const float*)d_in[3];
    float* out = (float*)d_out;
    (void)in_sizes; (void)n_in; (void)out_size;

    wconv_kernel<<<(192 * DM + 255) / 256, 256>>>(Wq, Wk, Wv);

    const int proj_smem = SM_ELEMS * (int)sizeof(__nv_bfloat16);   // 100 KB
    cudaFuncSetAttribute(proj_mma_kernel,
                         cudaFuncAttributeMaxDynamicSharedMemorySize, proj_smem);
    proj_mma_kernel<<<BT / BM, 256, proj_smem>>>(x);

    const int attn_smem = 2 * TT * DKV * (int)sizeof(float);       // 128 KB
    cudaFuncSetAttribute(attn_kernel,
                         cudaFuncAttributeMaxDynamicSharedMemorySize, attn_smem);
    attn_kernel<<<BATCH, 256, attn_smem>>>(out);
}

// round 5
// speedup vs baseline: 2.6537x; 1.8150x over previous
#include <cuda_runtime.h>
#include <cuda_bf16.h>
#include <cstdint>

// Problem constants
#define BATCH 256
#define TT    256
#define DM    384
#define DKV   64
#define BT    (BATCH*TT)

// ---------------------------------------------------------------------------
// Scratch
// ---------------------------------------------------------------------------
__device__ float g_q[BT * DKV];
__device__ float g_k[BT * DKV];
__device__ float g_v[BT * DKV];
// W^T packed [192 n][384 k], bf16 hi / lo split. n: 0-63=Wq, 64-127=Wk, 128-191=Wv
__device__ __align__(16) __nv_bfloat16 g_wth[192 * DM];
__device__ __align__(16) __nv_bfloat16 g_wtl[192 * DM];

// ---------------------------------------------------------------------------
// PTX helpers (sm_80-era: mma.sync + ldmatrix, valid at compute_103)
// ---------------------------------------------------------------------------
__device__ __forceinline__ uint32_t smem_u32(const void* p) {
    uint32_t a;
    asm("{ .reg .u64 t; cvta.to.shared.u64 t, %1; cvt.u32.u64 %0, t; }"
        : "=r"(a) : "l"(p));
    return a;
}
__device__ __forceinline__ void ldsm_x4(uint32_t addr, uint32_t* r) {
    asm volatile("ldmatrix.sync.aligned.m8n8.x4.shared.b16 {%0,%1,%2,%3}, [%4];"
                 : "=r"(r[0]), "=r"(r[1]), "=r"(r[2]), "=r"(r[3]) : "r"(addr));
}
__device__ __forceinline__ void ldsm_x4t(uint32_t addr, uint32_t* r) {
    asm volatile("ldmatrix.sync.aligned.m8n8.x4.trans.shared.b16 {%0,%1,%2,%3}, [%4];"
                 : "=r"(r[0]), "=r"(r[1]), "=r"(r[2]), "=r"(r[3]) : "r"(addr));
}
__device__ __forceinline__ void mma_bf16(float* c, const uint32_t* a,
                                         uint32_t b0, uint32_t b1) {
    asm volatile(
        "mma.sync.aligned.m16n8k16.row.col.f32.bf16.bf16.f32 "
        "{%0,%1,%2,%3}, {%4,%5,%6,%7}, {%8,%9}, {%0,%1,%2,%3};"
        : "+f"(c[0]), "+f"(c[1]), "+f"(c[2]), "+f"(c[3])
        : "r"(a[0]), "r"(a[1]), "r"(a[2]), "r"(a[3]), "r"(b0), "r"(b1));
}
__device__ __forceinline__ float ex2(float x) {
    float y;
    asm("ex2.approx.ftz.f32 %0, %1;" : "=f"(y) : "f"(x));
    return y;
}
// split float2 into packed bf16x2 hi and lo
__device__ __forceinline__ void split2(float x, float y, uint32_t& h, uint32_t& l) {
    __nv_bfloat16 h0 = __float2bfloat16(x), h1 = __float2bfloat16(y);
    __nv_bfloat16 l0 = __float2bfloat16(x - __bfloat162float(h0));
    __nv_bfloat16 l1 = __float2bfloat16(y - __bfloat162float(h1));
    __nv_bfloat162 hp = __halves2bfloat162(h0, h1);
    __nv_bfloat162 lp = __halves2bfloat162(l0, l1);
    h = *(uint32_t*)&hp; l = *(uint32_t*)&lp;
}

// ---------------------------------------------------------------------------
// Kernel 0: W^T hi/lo bf16 conversion
// ---------------------------------------------------------------------------
__global__ void wconv_kernel(const float* __restrict__ Wq,
                             const float* __restrict__ Wk,
                             const float* __restrict__ Wv) {
    int idx = blockIdx.x * 256 + threadIdx.x;
    if (idx >= 192 * DM) return;
    int n = idx / DM, k = idx % DM;
    const float* W = (n < 64) ? Wq : (n < 128) ? Wk : Wv;
    float x = W[k * DKV + (n & 63)];
    __nv_bfloat16 h = __float2bfloat16(x);
    g_wth[idx] = h;
    g_wtl[idx] = __float2bfloat16(x - __bfloat162float(h));
}

// ---------------------------------------------------------------------------
// Kernel 1: fused QKV projection via mma.sync bf16 (hi/lo 3-pass). Unchanged R4.
// ---------------------------------------------------------------------------
#define BM   128
#define BN   192
#define BKS  32
#define NKS  (DM / BKS)
#define PAD  40

#define A_SZ (BM * PAD)
#define B_SZ (BN * PAD)
#define OFF_AH(buf) ((buf) * A_SZ)
#define OFF_AL(buf) (2 * A_SZ + (buf) * A_SZ)
#define OFF_BH(buf) (4 * A_SZ + (buf) * B_SZ)
#define OFF_BL(buf) (4 * A_SZ + 2 * B_SZ + (buf) * B_SZ)
#define SM_ELEMS    (4 * A_SZ + 4 * B_SZ)

__global__ void __launch_bounds__(256, 1) proj_mma_kernel(const float* __restrict__ X) {
    extern __shared__ __nv_bfloat16 sm[];
    const uint32_t sb = smem_u32(sm);

    const int tid    = threadIdx.x;
    const int lane   = tid & 31;
    const int wid    = tid >> 5;
    const int warp_m = wid & 3;
    const int warp_n = wid >> 2;
    const int row0   = blockIdx.x * BM;

    float acc[2][12][4];
    #pragma unroll
    for (int m = 0; m < 2; m++)
        #pragma unroll
        for (int n = 0; n < 12; n++)
            #pragma unroll
            for (int j = 0; j < 4; j++) acc[m][n][j] = 0.f;

    float4 xa[4];
    uint4  bhs[3], bls[3];

    auto load_regs = [&](int ks) {
        const int k0 = ks * BKS;
        #pragma unroll
        for (int i = 0; i < 4; i++) {
            int f  = tid + i * 256;
            int r  = f >> 3;
            int c4 = f & 7;
            xa[i] = *(const float4*)(X + (size_t)(row0 + r) * DM + k0 + c4 * 4);
        }
        #pragma unroll
        for (int i = 0; i < 3; i++) {
            int f  = tid + i * 256;
            int r  = f >> 2;
            int c8 = f & 3;
            int e  = r * DM + k0 + c8 * 8;
            bhs[i] = *(const uint4*)(g_wth + e);
            bls[i] = *(const uint4*)(g_wtl + e);
        }
    };

    auto store_tile = [&](int buf) {
        #pragma unroll
        for (int i = 0; i < 4; i++) {
            int f  = tid + i * 256;
            int r  = f >> 3;
            int c4 = f & 7;
            float4 v = xa[i];
            uint32_t h0, l0, h1, l1;
            split2(v.x, v.y, h0, l0);
            split2(v.z, v.w, h1, l1);
            int e = r * PAD + c4 * 4;
            *(uint2*)(sm + OFF_AH(buf) + e) = make_uint2(h0, h1);
            *(uint2*)(sm + OFF_AL(buf) + e) = make_uint2(l0, l1);
        }
        #pragma unroll
        for (int i = 0; i < 3; i++) {
            int f  = tid + i * 256;
            int r  = f >> 2;
            int c8 = f & 3;
            int e  = r * PAD + c8 * 8;
            *(uint4*)(sm + OFF_BH(buf) + e) = bhs[i];
            *(uint4*)(sm + OFF_BL(buf) + e) = bls[i];
        }
    };

    load_regs(0);
    store_tile(0);
    __syncthreads();

    for (int ks = 0; ks < NKS; ks++) {
        const int cur = ks & 1;
        if (ks + 1 < NKS) load_regs(ks + 1);

        const uint32_t ah_base = sb + OFF_AH(cur) * 2;
        const uint32_t al_base = sb + OFF_AL(cur) * 2;
        const uint32_t bh_base = sb + OFF_BH(cur) * 2;
        const uint32_t bl_base = sb + OFF_BL(cur) * 2;

        #pragma unroll
        for (int kk = 0; kk < 2; kk++) {
            uint32_t ah[2][4], al[2][4];
            const int arow_l = (lane & 15);
            const int acol   = kk * 16 + ((lane >> 4) << 3);
            #pragma unroll
            for (int mt = 0; mt < 2; mt++) {
                const int arow = warp_m * 32 + mt * 16 + arow_l;
                const uint32_t aoff = (uint32_t)(arow * PAD + acol) * 2;
                ldsm_x4(ah_base + aoff, ah[mt]);
                ldsm_x4(al_base + aoff, al[mt]);
            }
            const int brow_l = (lane & 7) + ((lane & 16) >> 1);
            const int bcol   = kk * 16 + (lane & 8);
            #pragma unroll
            for (int g = 0; g < 6; g++) {
                uint32_t bh[4], bl[4];
                const int brow = warp_n * 96 + g * 16 + brow_l;
                const uint32_t boff = (uint32_t)(brow * PAD + bcol) * 2;
                ldsm_x4(bh_base + boff, bh);
                ldsm_x4(bl_base + boff, bl);
                #pragma unroll
                for (int mt = 0; mt < 2; mt++) {
                    #pragma unroll
                    for (int h = 0; h < 2; h++) {
                        float* c = acc[mt][g * 2 + h];
                        mma_bf16(c, ah[mt], bh[h * 2], bh[h * 2 + 1]);
                        mma_bf16(c, ah[mt], bl[h * 2], bl[h * 2 + 1]);
                        mma_bf16(c, al[mt], bh[h * 2], bh[h * 2 + 1]);
                    }
                }
            }
        }

        if (ks + 1 < NKS) {
            __syncthreads();
            store_tile(cur ^ 1);
            __syncthreads();
        }
    }

    const int gi = lane >> 2;
    const int ti = lane & 3;
    #pragma unroll
    for (int mt = 0; mt < 2; mt++) {
        const int row = row0 + warp_m * 32 + mt * 16 + gi;
        #pragma unroll
        for (int nt = 0; nt < 12; nt++) {
            const int col  = warp_n * 96 + nt * 8 + ti * 2;
            float* dstbase = (col < 64) ? g_q : (col < 128) ? g_k : g_v;
            float* d0 = dstbase + (size_t)row * DKV + (col & 63);
            float* d1 = dstbase + (size_t)(row + 8) * DKV + (col & 63);
            *(float2*)d0 = make_float2(acc[mt][nt][0], acc[mt][nt][1]);
            *(float2*)d1 = make_float2(acc[mt][nt][2], acc[mt][nt][3]);
        }
    }
}

// ---------------------------------------------------------------------------
// Kernel 2: causal attention on mma.sync (flash-style, hi/lo everywhere).
//   CTA = 1 batch. K,V hi/lo bf16 in smem (PAD 72 -> 144B stride, conflict-
//   free ldmatrix). Each warp: 32 queries (2 m16 tiles), loops its key
//   blocks of 16 independently (no syncs). Q frags from gmem; P frags
//   derived in-register from S accumulators. exp2-domain online softmax.
// ---------------------------------------------------------------------------
#define APAD 72
#define KV_SZ (TT * APAD)       // 18432 elems per buffer

__global__ void __launch_bounds__(256, 1) attn_mma_kernel(float* __restrict__ out) {
    extern __shared__ __nv_bfloat16 smk[];
    __nv_bfloat16* Kh = smk;
    __nv_bfloat16* Kl = smk + KV_SZ;
    __nv_bfloat16* Vh = smk + 2 * KV_SZ;
    __nv_bfloat16* Vl = smk + 3 * KV_SZ;

    const int b    = blockIdx.x;
    const int tid  = threadIdx.x;
    const int lane = tid & 31;
    const int wid  = tid >> 5;

    // ---- prologue: K,V fp32 -> smem bf16 hi/lo ----
    {
        const float4* Kg = (const float4*)(g_k + (size_t)b * TT * DKV);
        const float4* Vg = (const float4*)(g_v + (size_t)b * TT * DKV);
        #pragma unroll
        for (int i0 = 0; i0 < 16; i0++) {
            int i = tid + i0 * 256;           // 0..4095
            int r = i >> 4, c4 = (i & 15) * 4;
            int e = r * APAD + c4;
            float4 kv = Kg[i];
            uint32_t h0, l0, h1, l1;
            split2(kv.x, kv.y, h0, l0);
            split2(kv.z, kv.w, h1, l1);
            *(uint2*)(Kh + e) = make_uint2(h0, h1);
            *(uint2*)(Kl + e) = make_uint2(l0, l1);
            float4 vv = Vg[i];
            split2(vv.x, vv.y, h0, l0);
            split2(vv.z, vv.w, h1, l1);
            *(uint2*)(Vh + e) = make_uint2(h0, h1);
            *(uint2*)(Vl + e) = make_uint2(l0, l1);
        }
    }

    // ---- Q fragments (gmem -> regs), scaled by 0.125*log2(e) ----
    const int qb = (wid < 4) ? wid : (11 - wid);   // SMSP balance: pairs sum 288
    const int Q0 = qb * 32;
    const int g  = lane >> 2;
    const int tg = lane & 3;
    const float SC = 0.125f * 1.44269504f;

    uint32_t qh[2][4][4], ql[2][4][4];
    {
        const float* Qb = g_q + ((size_t)b * TT + Q0) * DKV;
        #pragma unroll
        for (int mt = 0; mt < 2; mt++) {
            #pragma unroll
            for (int kk = 0; kk < 4; kk++) {
                const int r0 = mt * 16 + g;
                const int c0 = kk * 16 + tg * 2;
                float2 v00 = *(const float2*)(Qb + r0 * DKV + c0);
                float2 v01 = *(const float2*)(Qb + r0 * DKV + c0 + 8);
                float2 v10 = *(const float2*)(Qb + (r0 + 8) * DKV + c0);
                float2 v11 = *(const float2*)(Qb + (r0 + 8) * DKV + c0 + 8);
                split2(v00.x * SC, v00.y * SC, qh[mt][kk][0], ql[mt][kk][0]);
                split2(v10.x * SC, v10.y * SC, qh[mt][kk][1], ql[mt][kk][1]);
                split2(v01.x * SC, v01.y * SC, qh[mt][kk][2], ql[mt][kk][2]);
                split2(v11.x * SC, v11.y * SC, qh[mt][kk][3], ql[mt][kk][3]);
            }
        }
    }
    __syncthreads();

    const uint32_t sbKh = smem_u32(Kh), sbKl = smem_u32(Kl);
    const uint32_t sbVh = smem_u32(Vh), sbVl = smem_u32(Vl);

    float m[4] = {-1e30f, -1e30f, -1e30f, -1e30f};
    float lsum[4] = {0.f, 0.f, 0.f, 0.f};
    float O[2][8][4];
    #pragma unroll
    for (int mt = 0; mt < 2; mt++)
        #pragma unroll
        for (int n = 0; n < 8; n++)
            #pragma unroll
            for (int j = 0; j < 4; j++) O[mt][n][j] = 0.f;

    const int krow = (lane & 7) + ((lane & 16) >> 1);   // K/B frag row
    const int koff = (lane & 8);                        // k-offset within k16
    const int vkey = lane & 15;                         // V/B trans frag row
    const int voff = (lane >> 4) << 3;                  // n-offset

    const int nblk = qb * 2 + 2;
    for (int kb = 0; kb < nblk; kb++) {
        const int j0 = kb * 16;
        const bool msk = (kb >= qb * 2);

        // ---- S = Q K^T (hi/lo 3-pass) ----
        float S[2][2][4];
        #pragma unroll
        for (int mt = 0; mt < 2; mt++)
            #pragma unroll
            for (int nt = 0; nt < 2; nt++)
                #pragma unroll
                for (int j = 0; j < 4; j++) S[mt][nt][j] = 0.f;

        const uint32_t kb_h = sbKh + (uint32_t)((j0 + krow) * APAD + koff) * 2;
        const uint32_t kb_l = sbKl + (uint32_t)((j0 + krow) * APAD + koff) * 2;
        #pragma unroll
        for (int kk = 0; kk < 4; kk++) {
            uint32_t bh[4], bl[4];
            ldsm_x4(kb_h + kk * 32, bh);
            ldsm_x4(kb_l + kk * 32, bl);
            #pragma unroll
            for (int mt = 0; mt < 2; mt++) {
                mma_bf16(S[mt][0], qh[mt][kk], bh[0], bh[1]);
                mma_bf16(S[mt][1], qh[mt][kk], bh[2], bh[3]);
                mma_bf16(S[mt][0], qh[mt][kk], bl[0], bl[1]);
                mma_bf16(S[mt][1], qh[mt][kk], bl[2], bl[3]);
                mma_bf16(S[mt][0], ql[mt][kk], bh[0], bh[1]);
                mma_bf16(S[mt][1], ql[mt][kk], bh[2], bh[3]);
            }
        }

        // ---- causal mask ----
        if (msk) {
            #pragma unroll
            for (int mt = 0; mt < 2; mt++)
                #pragma unroll
                for (int nt = 0; nt < 2; nt++)
                    #pragma unroll
                    for (int j = 0; j < 4; j++) {
                        const int row = Q0 + mt * 16 + g + ((j >> 1) << 3);
                        const int col = j0 + nt * 8 + tg * 2 + (j & 1);
                        if (col > row) S[mt][nt][j] = -1e30f;
                    }
        }

        // ---- online softmax + P frag build ----
        uint32_t pah[2][4], pal[2][4];
        #pragma unroll
        for (int mt = 0; mt < 2; mt++) {
            #pragma unroll
            for (int h = 0; h < 2; h++) {
                const int rg = mt * 2 + h;
                float v0 = S[mt][0][h * 2], v1 = S[mt][0][h * 2 + 1];
                float v2 = S[mt][1][h * 2], v3 = S[mt][1][h * 2 + 1];
                float mx = fmaxf(fmaxf(v0, v1), fmaxf(v2, v3));
                mx = fmaxf(mx, __shfl_xor_sync(0xFFFFFFFFu, mx, 1));
                mx = fmaxf(mx, __shfl_xor_sync(0xFFFFFFFFu, mx, 2));
                const float mnew = fmaxf(m[rg], mx);
                const float sc   = ex2(m[rg] - mnew);
                m[rg] = mnew;
                const float p0 = ex2(v0 - mnew), p1 = ex2(v1 - mnew);
                const float p2 = ex2(v2 - mnew), p3 = ex2(v3 - mnew);
                lsum[rg] = lsum[rg] * sc + (p0 + p1 + p2 + p3);
                #pragma unroll
                for (int n = 0; n < 8; n++) {
                    O[mt][n][h * 2]     *= sc;
                    O[mt][n][h * 2 + 1] *= sc;
                }
                split2(p0, p1, pah[mt][h],     pal[mt][h]);
                split2(p2, p3, pah[mt][2 + h], pal[mt][2 + h]);
            }
        }

        // ---- O += P V (hi/lo 3-pass) ----
        const uint32_t vb_h = sbVh + (uint32_t)((j0 + vkey) * APAD + voff) * 2;
        const uint32_t vb_l = sbVl + (uint32_t)((j0 + vkey) * APAD + voff) * 2;
        #pragma unroll
        for (int nc = 0; nc < 4; nc++) {
            uint32_t vh4[4], vl4[4];
            ldsm_x4t(vb_h + nc * 32, vh4);
            ldsm_x4t(vb_l + nc * 32, vl4);
            #pragma unroll
            for (int mt = 0; mt < 2; mt++) {
                mma_bf16(O[mt][nc * 2],     pah[mt], vh4[0], vh4[1]);
                mma_bf16(O[mt][nc * 2 + 1], pah[mt], vh4[2], vh4[3]);
                mma_bf16(O[mt][nc * 2],     pal[mt], vh4[0], vh4[1]);
                mma_bf16(O[mt][nc * 2 + 1], pal[mt], vh4[2], vh4[3]);
                mma_bf16(O[mt][nc * 2],     pah[mt], vl4[0], vl4[1]);
                mma_bf16(O[mt][nc * 2 + 1], pah[mt], vl4[2], vl4[3]);
            }
        }
    }

    // ---- epilogue: quad-reduce l, normalize, store ----
    float inv[4];
    #pragma unroll
    for (int rg = 0; rg < 4; rg++) {
        float ls = lsum[rg];
        ls += __shfl_xor_sync(0xFFFFFFFFu, ls, 1);
        ls += __shfl_xor_sync(0xFFFFFFFFu, ls, 2);
        inv[rg] = 1.f / ls;
    }
    float* ob = out + ((size_t)b * TT) * DKV;
    #pragma unroll
    for (int mt = 0; mt < 2; mt++) {
        #pragma unroll
        for (int h = 0; h < 2; h++) {
            const int row = Q0 + mt * 16 + g + h * 8;
            const float iv = inv[mt * 2 + h];
            #pragma unroll
            for (int n = 0; n < 8; n++) {
                *(float2*)(ob + (size_t)row * DKV + n * 8 + tg * 2) =
                    make_float2(O[mt][n][h * 2] * iv, O[mt][n][h * 2 + 1] * iv);
            }
        }
    }
}

// ---------------------------------------------------------------------------
// kernel_launch — graph-capturable, allocation-free
// ---------------------------------------------------------------------------
extern "C" void kernel_launch(void* const* d_in, const int* in_sizes, int n_in,
                              void* d_out, int out_size) {
    const float* x  = (const float*)d_in[0];
    const float* Wq = (const float*)d_in[1];
    const float* Wk = (const float*)d_in[2];
    const float* Wv = (const float*)d_in[3];
    float* out = (float*)d_out;
    (void)in_sizes; (void)n_in; (void)out_size;

    wconv_kernel<<<(192 * DM + 255) / 256, 256>>>(Wq, Wk, Wv);

    const int proj_smem = SM_ELEMS * (int)sizeof(__nv_bfloat16);   // 100 KB
    cudaFuncSetAttribute(proj_mma_kernel,
                         cudaFuncAttributeMaxDynamicSharedMemorySize, proj_smem);
    proj_mma_kernel<<<BT / BM, 256, proj_smem>>>(x);

    const int attn_smem = 4 * KV_SZ * (int)sizeof(__nv_bfloat16);  // 144 KB
    cudaFuncSetAttribute(attn_mma_kernel,
                         cudaFuncAttributeMaxDynamicSharedMemorySize, attn_smem);
    attn_mma_kernel<<<BATCH, 256, attn_smem>>>(out);
}